// round 2
// baseline (speedup 1.0000x reference)
#include <cuda_runtime.h>
#include <math.h>

#define BB 8
#define TT 4096
#define NM 1024
#define DD 128

// Scratch: k_rot (acts as Q and K) and v (= k pre-RoPE)
__device__ float g_k[BB * TT * DD];
__device__ float g_v[BB * TT * DD];

// ---------------------------------------------------------------------------
// Kernel 1: k = x @ W_K^T, then position-independent RoPE (in-place semantics)
// grid = 512 blocks (64 rows each), 256 threads.
// Thread (ty,tx): rows r = ty + 16*i (i<4), cols c = tx + 16*j (j<8).
// ---------------------------------------------------------------------------
__global__ __launch_bounds__(256) void proj_rope_kernel(
    const float* __restrict__ x, const float* __restrict__ W) {
    __shared__ float sX[64 * 33];
    __shared__ float sW[128 * 33];

    const int tid = threadIdx.x;
    const int tx = tid & 15;
    const int ty = tid >> 4;
    const int m0 = blockIdx.x * 64;

    float acc[4][8];
#pragma unroll
    for (int i = 0; i < 4; i++)
#pragma unroll
        for (int j = 0; j < 8; j++) acc[i][j] = 0.f;

    const int kk = tid & 31;
    const int rr = tid >> 5;

    for (int k0 = 0; k0 < NM; k0 += 32) {
        __syncthreads();
#pragma unroll
        for (int p = 0; p < 8; p++) {
            int r = rr + 8 * p;
            sX[r * 33 + kk] = x[(size_t)(m0 + r) * NM + k0 + kk];
        }
#pragma unroll
        for (int p = 0; p < 16; p++) {
            int r = rr + 8 * p;
            sW[r * 33 + kk] = W[(size_t)r * NM + k0 + kk];
        }
        __syncthreads();

#pragma unroll 8
        for (int q = 0; q < 32; q++) {
            float a[4], b[8];
#pragma unroll
            for (int i = 0; i < 4; i++) a[i] = sX[(ty + 16 * i) * 33 + q];
#pragma unroll
            for (int j = 0; j < 8; j++) b[j] = sW[(tx + 16 * j) * 33 + q];
#pragma unroll
            for (int i = 0; i < 4; i++)
#pragma unroll
                for (int j = 0; j < 8; j++) acc[i][j] = fmaf(a[i], b[j], acc[i][j]);
        }
    }

    // RoPE epilogue. Pair (2h, 2h+1) spans lanes (tx even, tx odd) -> shfl.xor(1).
#pragma unroll
    for (int i = 0; i < 4; i++) {
        int row = m0 + ty + 16 * i;
#pragma unroll
        for (int j = 0; j < 8; j++) {
            int col = tx + 16 * j;
            float val = acc[i][j];
            float other = __shfl_xor_sync(0xffffffffu, val, 1);
            int h = col >> 1;
            float ang = powf(10000.0f, -(float)h * (1.0f / 64.0f));
            float c = cosf(ang), s = sinf(ang);
            // even lane: val=t1, other=t2 -> even' = t1*c + t2*s
            float evenp = fmaf(val, c, other * s);
            float evenp_nb = __shfl_xor_sync(0xffffffffu, evenp, 1);
            // odd lane: val=t2, partner's even' -> odd' = -even'*s + t2*c
            float rot = (col & 1) ? fmaf(-evenp_nb, s, val * c) : evenp;
            g_v[(size_t)row * DD + col] = val;
            g_k[(size_t)row * DD + col] = rot;
        }
    }
}

// ---------------------------------------------------------------------------
// Kernel 2: causal flash attention, Q = K = g_k, V = g_v.
// BLOCK_M = BLOCK_N = 64, 256 threads, fp32.
// Thread (ty,tx):
//   S tile  : rows r = ty+16i (i<4), cols c = tx+16j (j<4)      [strided]
//   O tile  : rows r = ty+16i (i<4), cols c = 4tx+j (j<4) and
//             c = 64+4tx+j (j<4)                                 [2x float4]
// smem: sQ 64x128 | sK 64x132 | sV 64x132 | sP 64x64  = 116736 B (2 CTA/SM).
// ---------------------------------------------------------------------------
#define PADK 132
#define PADV 132
#define ATT_SMEM ((64 * 128 + 64 * PADK + 64 * PADV + 64 * 64) * 4)

__global__ __launch_bounds__(256, 2) void attn_kernel(float* __restrict__ out) {
    extern __shared__ float sm[];
    float* sQ = sm;                       // 64*128
    float* sK = sQ + 64 * 128;            // 64*PADK
    float* sV = sK + 64 * PADK;           // 64*PADV
    float* sP = sV + 64 * PADV;           // 64*64

    const int tid = threadIdx.x;
    const int tx = tid & 15;
    const int ty = tid >> 4;
    const int b = blockIdx.y;
    const int i_tile = 63 - (int)blockIdx.x;   // heavy tiles launch first
    const int q0 = i_tile * 64;

    const float* __restrict__ Kb = g_k + (size_t)b * TT * DD;
    const float* __restrict__ Vb = g_v + (size_t)b * TT * DD;

    const float SCALE = 0.08838834764831845f;  // 128^-0.5
    const int k4 = (tid & 31) * 4;
    const int rr = tid >> 5;

    // Load Q tile, pre-scaled by 1/sqrt(D)
#pragma unroll
    for (int p = 0; p < 8; p++) {
        int r = rr + 8 * p;
        float4 v = *(const float4*)&Kb[(size_t)(q0 + r) * DD + k4];
        v.x *= SCALE; v.y *= SCALE; v.z *= SCALE; v.w *= SCALE;
        *(float4*)&sQ[r * DD + k4] = v;
    }

    float O[4][8];   // [i][j]: cols 4tx+j (j<4), 64+4tx+(j-4) (j>=4)
    float m_i[4], l_i[4];
#pragma unroll
    for (int i = 0; i < 4; i++) {
        m_i[i] = -__int_as_float(0x7f800000);  // -inf
        l_i[i] = 0.f;
#pragma unroll
        for (int j = 0; j < 8; j++) O[i][j] = 0.f;
    }

    for (int jt = 0; jt <= i_tile; jt++) {
        const int j0 = jt * 64;
        __syncthreads();  // prior iter done with sK/sV (and orders Q stores on iter 0)
#pragma unroll
        for (int p = 0; p < 8; p++) {
            int r = rr + 8 * p;
            float4 kv = *(const float4*)&Kb[(size_t)(j0 + r) * DD + k4];
            *(float4*)&sK[r * PADK + k4] = kv;
            float4 vv = *(const float4*)&Vb[(size_t)(j0 + r) * DD + k4];
            *(float4*)&sV[r * PADV + k4] = vv;
        }
        __syncthreads();

        // ---- S = Qs @ K^T  (4x4 per thread, strided cols tx+16j) ----
        float s[4][4];
#pragma unroll
        for (int i = 0; i < 4; i++)
#pragma unroll
            for (int j = 0; j < 4; j++) s[i][j] = 0.f;

#pragma unroll 4
        for (int k0 = 0; k0 < DD; k0 += 4) {
            float4 qf[4], kf[4];
#pragma unroll
            for (int i = 0; i < 4; i++) qf[i] = *(const float4*)&sQ[(ty + 16 * i) * DD + k0];
#pragma unroll
            for (int j = 0; j < 4; j++) kf[j] = *(const float4*)&sK[(tx + 16 * j) * PADK + k0];
#pragma unroll
            for (int i = 0; i < 4; i++)
#pragma unroll
                for (int j = 0; j < 4; j++) {
                    s[i][j] = fmaf(qf[i].x, kf[j].x, s[i][j]);
                    s[i][j] = fmaf(qf[i].y, kf[j].y, s[i][j]);
                    s[i][j] = fmaf(qf[i].z, kf[j].z, s[i][j]);
                    s[i][j] = fmaf(qf[i].w, kf[j].w, s[i][j]);
                }
        }

        // Causal mask on the diagonal tile
        if (jt == i_tile) {
#pragma unroll
            for (int i = 0; i < 4; i++)
#pragma unroll
                for (int j = 0; j < 4; j++)
                    if ((tx + 16 * j) > (ty + 16 * i)) s[i][j] = -__int_as_float(0x7f800000);
        }

        // ---- online softmax update ----
#pragma unroll
        for (int i = 0; i < 4; i++) {
            float t = fmaxf(fmaxf(s[i][0], s[i][1]), fmaxf(s[i][2], s[i][3]));
#pragma unroll
            for (int off = 8; off >= 1; off >>= 1)
                t = fmaxf(t, __shfl_xor_sync(0xffffffffu, t, off));
            float mnew = fmaxf(m_i[i], t);
            float sc = __expf(m_i[i] - mnew);
            float r = 0.f;
#pragma unroll
            for (int j = 0; j < 4; j++) {
                s[i][j] = __expf(s[i][j] - mnew);
                r += s[i][j];
            }
#pragma unroll
            for (int off = 8; off >= 1; off >>= 1)
                r += __shfl_xor_sync(0xffffffffu, r, off);
            l_i[i] = l_i[i] * sc + r;
            m_i[i] = mnew;
#pragma unroll
            for (int j = 0; j < 8; j++) O[i][j] *= sc;
        }

        // ---- P -> smem (same half-warp produces & consumes each row) ----
#pragma unroll
        for (int i = 0; i < 4; i++)
#pragma unroll
            for (int j = 0; j < 4; j++)
                sP[(ty + 16 * i) * 64 + tx + 16 * j] = s[i][j];
        __syncwarp();

        // ---- O += P @ V (vectorized: P float4 over n, V two float4 per n) ----
#pragma unroll
        for (int n0 = 0; n0 < 64; n0 += 4) {
            float4 pf[4];
#pragma unroll
            for (int i = 0; i < 4; i++)
                pf[i] = *(const float4*)&sP[(ty + 16 * i) * 64 + n0];
            float pa[4][4];
#pragma unroll
            for (int i = 0; i < 4; i++) {
                pa[i][0] = pf[i].x; pa[i][1] = pf[i].y;
                pa[i][2] = pf[i].z; pa[i][3] = pf[i].w;
            }
#pragma unroll
            for (int dn = 0; dn < 4; dn++) {
                const int n = n0 + dn;
                float4 va = *(const float4*)&sV[n * PADV + 4 * tx];
                float4 vb = *(const float4*)&sV[n * PADV + 64 + 4 * tx];
#pragma unroll
                for (int i = 0; i < 4; i++) {
                    float p = pa[i][dn];
                    O[i][0] = fmaf(p, va.x, O[i][0]);
                    O[i][1] = fmaf(p, va.y, O[i][1]);
                    O[i][2] = fmaf(p, va.z, O[i][2]);
                    O[i][3] = fmaf(p, va.w, O[i][3]);
                    O[i][4] = fmaf(p, vb.x, O[i][4]);
                    O[i][5] = fmaf(p, vb.y, O[i][5]);
                    O[i][6] = fmaf(p, vb.z, O[i][6]);
                    O[i][7] = fmaf(p, vb.w, O[i][7]);
                }
            }
        }
    }

    // ---- epilogue: normalize and store (two coalesced float4 per row) ----
#pragma unroll
    for (int i = 0; i < 4; i++) {
        float inv = 1.0f / l_i[i];
        size_t row = (size_t)b * TT + q0 + ty + 16 * i;
        float4 o0 = make_float4(O[i][0] * inv, O[i][1] * inv,
                                O[i][2] * inv, O[i][3] * inv);
        float4 o1 = make_float4(O[i][4] * inv, O[i][5] * inv,
                                O[i][6] * inv, O[i][7] * inv);
        *(float4*)&out[row * DD + 4 * tx] = o0;
        *(float4*)&out[row * DD + 64 + 4 * tx] = o1;
    }
}

// ---------------------------------------------------------------------------
extern "C" void kernel_launch(void* const* d_in, const int* in_sizes, int n_in,
                              void* d_out, int out_size) {
    const float* x = (const float*)d_in[0];   // [8, 4096, 1024] fp32
    const float* W = (const float*)d_in[1];   // [128, 1024] fp32
    float* out = (float*)d_out;               // [8, 4096, 128] fp32

    cudaFuncSetAttribute(attn_kernel, cudaFuncAttributeMaxDynamicSharedMemorySize,
                         ATT_SMEM);

    proj_rope_kernel<<<(BB * TT) / 64, 256>>>(x, W);
    attn_kernel<<<dim3(64, BB), 256, ATT_SMEM>>>(out);
}

// round 4
// speedup vs baseline: 1.9076x; 1.9076x over previous
#include <cuda_runtime.h>
#include <math.h>
#include <stdint.h>

#define BB 8
#define TT 4096
#define NM 1024
#define DD 128

// Scratch: k_rot (acts as Q and K) and v (= k pre-RoPE)
__device__ float g_k[BB * TT * DD];
__device__ float g_v[BB * TT * DD];

__device__ __forceinline__ uint32_t f2tf(float x) {
    uint32_t r;
    asm("cvt.rna.tf32.f32 %0, %1;" : "=r"(r) : "f"(x));
    return r;
}

__device__ __forceinline__ void mma_tf32(float* c, const uint32_t* a,
                                         uint32_t b0, uint32_t b1) {
    asm volatile(
        "mma.sync.aligned.m16n8k8.row.col.f32.tf32.tf32.f32 "
        "{%0,%1,%2,%3}, {%4,%5,%6,%7}, {%8,%9}, {%0,%1,%2,%3};\n"
        : "+f"(c[0]), "+f"(c[1]), "+f"(c[2]), "+f"(c[3])
        : "r"(a[0]), "r"(a[1]), "r"(a[2]), "r"(a[3]), "r"(b0), "r"(b1));
}

// ---------------------------------------------------------------------------
// Kernel 1: k = x @ W_K^T via tf32 mma (2-pass split on x, W tf32-rounded),
// then position-independent RoPE (in-place semantics) fused in the epilogue.
// CTA = 128 threads (4 warps), 64 rows, full N=128, K chunks of 32.
// C-fragment cols (2t, 2t+1) are adjacent -> RoPE pair lives in one thread.
// ---------------------------------------------------------------------------
__global__ __launch_bounds__(128) void proj_rope_kernel(
    const float* __restrict__ x, const float* __restrict__ W) {
    __shared__ float sX[64 * 36];       // fp32 (exact, for hi/lo split)
    __shared__ uint32_t sWu[128 * 36];  // tf32-rounded

    const int tid = threadIdx.x;
    const int w = tid >> 5;
    const int lane = tid & 31;
    const int g = lane >> 2;
    const int t = lane & 3;
    const int mBase = w * 16;
    const int m0 = blockIdx.x * 64;

    float c[16][4];
#pragma unroll
    for (int nt = 0; nt < 16; nt++)
#pragma unroll
        for (int e = 0; e < 4; e++) c[nt][e] = 0.f;

    for (int kc = 0; kc < NM; kc += 32) {
        __syncthreads();
        // x chunk: 64x32 floats
#pragma unroll
        for (int p = 0; p < 4; p++) {
            int idx = tid + 128 * p;          // float4 units, 0..511
            int row = idx >> 3;
            int c4 = (idx & 7) * 4;
            *(float4*)&sX[row * 36 + c4] =
                *(const float4*)&x[(size_t)(m0 + row) * NM + kc + c4];
        }
        // W chunk: 128x32, tf32-rounded
#pragma unroll
        for (int p = 0; p < 8; p++) {
            int idx = tid + 128 * p;          // 0..1023
            int row = idx >> 3;
            int c4 = (idx & 7) * 4;
            float4 wv = *(const float4*)&W[(size_t)row * NM + kc + c4];
            uint4 wu = make_uint4(f2tf(wv.x), f2tf(wv.y), f2tf(wv.z), f2tf(wv.w));
            *(uint4*)&sWu[row * 36 + c4] = wu;
        }
        __syncthreads();

#pragma unroll
        for (int kt = 0; kt < 4; kt++) {
            const int k0 = kt * 8;
            float a0 = sX[(mBase + g) * 36 + k0 + t];
            float a1 = sX[(mBase + g + 8) * 36 + k0 + t];
            float a2 = sX[(mBase + g) * 36 + k0 + t + 4];
            float a3 = sX[(mBase + g + 8) * 36 + k0 + t + 4];
            uint32_t ahi[4], alo[4];
            ahi[0] = f2tf(a0); ahi[1] = f2tf(a1);
            ahi[2] = f2tf(a2); ahi[3] = f2tf(a3);
            alo[0] = f2tf(a0 - __uint_as_float(ahi[0]));
            alo[1] = f2tf(a1 - __uint_as_float(ahi[1]));
            alo[2] = f2tf(a2 - __uint_as_float(ahi[2]));
            alo[3] = f2tf(a3 - __uint_as_float(ahi[3]));
#pragma unroll
            for (int nt = 0; nt < 16; nt++) {
                uint32_t b0 = sWu[(nt * 8 + g) * 36 + k0 + t];
                uint32_t b1 = sWu[(nt * 8 + g) * 36 + k0 + t + 4];
                mma_tf32(c[nt], ahi, b0, b1);
                mma_tf32(c[nt], alo, b0, b1);
            }
        }
    }

    // ---- RoPE epilogue (pair = adjacent cols, same thread) + store ----
    const size_t row0 = (size_t)(m0 + mBase + g);
    const size_t row1 = row0 + 8;
#pragma unroll
    for (int nt = 0; nt < 16; nt++) {
        int col = nt * 8 + 2 * t;
        int h = col >> 1;
        float ang = powf(10000.0f, -(float)h * (1.0f / 64.0f));
        float cc = cosf(ang), ss = sinf(ang);
        // row0: t1 = c[nt][0], t2 = c[nt][1]
        float e0 = fmaf(c[nt][0], cc, c[nt][1] * ss);
        float o0 = fmaf(-e0, ss, c[nt][1] * cc);
        // row1: t1 = c[nt][2], t2 = c[nt][3]
        float e1 = fmaf(c[nt][2], cc, c[nt][3] * ss);
        float o1 = fmaf(-e1, ss, c[nt][3] * cc);
        *(float2*)&g_v[row0 * DD + col] = make_float2(c[nt][0], c[nt][1]);
        *(float2*)&g_v[row1 * DD + col] = make_float2(c[nt][2], c[nt][3]);
        *(float2*)&g_k[row0 * DD + col] = make_float2(e0, o0);
        *(float2*)&g_k[row1 * DD + col] = make_float2(e1, o1);
    }
}

// ---------------------------------------------------------------------------
// Kernel 2: causal flash attention with tf32 mma.sync (2-pass split precision)
// CTA = 128 threads (4 warps). BLOCK_M=64 (16 rows/warp), BLOCK_N=64, D=128.
// smem: sQf fp32 [64][132] | sKu tf32 [64][132] | sVu tf32 [64][136]
//       | sP 4 x [16][12]  = 105472 B -> 2 CTAs/SM.
// ---------------------------------------------------------------------------
#define QSTR 132
#define KSTR 132
#define VSTR 136
#define OFF_K (64 * QSTR)
#define OFF_V (OFF_K + 64 * KSTR)
#define OFF_P (OFF_V + 64 * VSTR)
#define ATT_SMEM ((OFF_P + 4 * 16 * 12) * 4)

__global__ __launch_bounds__(128, 2) void attn_kernel(float* __restrict__ out) {
    extern __shared__ float sm[];
    float* sQf = sm;
    uint32_t* sKu = (uint32_t*)(sm + OFF_K);
    uint32_t* sVu = (uint32_t*)(sm + OFF_V);
    float* sP = sm + OFF_P;

    const int tid = threadIdx.x;
    const int w = tid >> 5;
    const int lane = tid & 31;
    const int g = lane >> 2;
    const int t = lane & 3;
    const int mBase = w * 16;

    const int b = blockIdx.y;
    const int i_tile = 63 - (int)blockIdx.x;
    const int q0 = i_tile * 64;

    const float* __restrict__ Kb = g_k + (size_t)b * TT * DD;
    const float* __restrict__ Vb = g_v + (size_t)b * TT * DD;
    float* sPw = sP + w * 16 * 12;

    const float SCALE = 0.08838834764831845f;  // 128^-0.5
    const float NEG_INF = __int_as_float(0xff800000);

    // ---- fill sQ (fp32, pre-scaled) ----
#pragma unroll
    for (int p = 0; p < 16; p++) {
        int idx = tid + 128 * p;
        int row = idx >> 5;
        int c4 = (idx & 31) * 4;
        float4 v = *(const float4*)&Kb[(size_t)(q0 + row) * DD + c4];
        v.x *= SCALE; v.y *= SCALE; v.z *= SCALE; v.w *= SCALE;
        *(float4*)&sQf[row * QSTR + c4] = v;
    }

    float O[16][4];
    float m_i[2], l_i[2];
#pragma unroll
    for (int nt = 0; nt < 16; nt++)
#pragma unroll
        for (int e = 0; e < 4; e++) O[nt][e] = 0.f;
    m_i[0] = NEG_INF; m_i[1] = NEG_INF;
    l_i[0] = 0.f; l_i[1] = 0.f;

    for (int jt = 0; jt <= i_tile; jt++) {
        const int j0 = jt * 64;
        __syncthreads();  // prior iter done with sK/sV (also orders sQ fill)

#pragma unroll
        for (int p = 0; p < 16; p++) {
            int idx = tid + 128 * p;
            int row = idx >> 5;
            int c4 = (idx & 31) * 4;
            float4 kv = *(const float4*)&Kb[(size_t)(j0 + row) * DD + c4];
            uint4 ku = make_uint4(f2tf(kv.x), f2tf(kv.y), f2tf(kv.z), f2tf(kv.w));
            *(uint4*)&sKu[row * KSTR + c4] = ku;
            float4 vv = *(const float4*)&Vb[(size_t)(j0 + row) * DD + c4];
            uint4 vu = make_uint4(f2tf(vv.x), f2tf(vv.y), f2tf(vv.z), f2tf(vv.w));
            *(uint4*)&sVu[row * VSTR + c4] = vu;
        }
        __syncthreads();

        // ---- S = Q K^T ----
        float c[8][4];
#pragma unroll
        for (int nt = 0; nt < 8; nt++)
#pragma unroll
            for (int e = 0; e < 4; e++) c[nt][e] = 0.f;

#pragma unroll 4
        for (int kt = 0; kt < 16; kt++) {
            const int k0 = kt * 8;
            float qa0 = sQf[(mBase + g) * QSTR + k0 + t];
            float qa1 = sQf[(mBase + g + 8) * QSTR + k0 + t];
            float qa2 = sQf[(mBase + g) * QSTR + k0 + t + 4];
            float qa3 = sQf[(mBase + g + 8) * QSTR + k0 + t + 4];
            uint32_t ahi[4], alo[4];
            ahi[0] = f2tf(qa0); ahi[1] = f2tf(qa1);
            ahi[2] = f2tf(qa2); ahi[3] = f2tf(qa3);
            alo[0] = f2tf(qa0 - __uint_as_float(ahi[0]));
            alo[1] = f2tf(qa1 - __uint_as_float(ahi[1]));
            alo[2] = f2tf(qa2 - __uint_as_float(ahi[2]));
            alo[3] = f2tf(qa3 - __uint_as_float(ahi[3]));
#pragma unroll
            for (int nt = 0; nt < 8; nt++) {
                uint32_t b0 = sKu[(nt * 8 + g) * KSTR + k0 + t];
                uint32_t b1 = sKu[(nt * 8 + g) * KSTR + k0 + t + 4];
                mma_tf32(c[nt], ahi, b0, b1);
                mma_tf32(c[nt], alo, b0, b1);
            }
        }

        // ---- causal mask on the diagonal tile ----
        if (jt == i_tile) {
            const int r0 = mBase + g;
            const int r1 = mBase + g + 8;
#pragma unroll
            for (int nt = 0; nt < 8; nt++) {
                int c0 = nt * 8 + 2 * t;
                if (c0 > r0) c[nt][0] = NEG_INF;
                if (c0 + 1 > r0) c[nt][1] = NEG_INF;
                if (c0 > r1) c[nt][2] = NEG_INF;
                if (c0 + 1 > r1) c[nt][3] = NEG_INF;
            }
        }

        // ---- online softmax (rows g and g+8) ----
#pragma unroll
        for (int ri = 0; ri < 2; ri++) {
            float mx = NEG_INF;
#pragma unroll
            for (int nt = 0; nt < 8; nt++)
                mx = fmaxf(mx, fmaxf(c[nt][2 * ri], c[nt][2 * ri + 1]));
            mx = fmaxf(mx, __shfl_xor_sync(0xffffffffu, mx, 1));
            mx = fmaxf(mx, __shfl_xor_sync(0xffffffffu, mx, 2));
            float mnew = fmaxf(m_i[ri], mx);
            float sc = __expf(m_i[ri] - mnew);
            float rsum = 0.f;
#pragma unroll
            for (int nt = 0; nt < 8; nt++) {
                c[nt][2 * ri] = __expf(c[nt][2 * ri] - mnew);
                c[nt][2 * ri + 1] = __expf(c[nt][2 * ri + 1] - mnew);
                rsum += c[nt][2 * ri] + c[nt][2 * ri + 1];
            }
            rsum += __shfl_xor_sync(0xffffffffu, rsum, 1);
            rsum += __shfl_xor_sync(0xffffffffu, rsum, 2);
            l_i[ri] = l_i[ri] * sc + rsum;
            m_i[ri] = mnew;
#pragma unroll
            for (int nt = 0; nt < 16; nt++) {
                O[nt][2 * ri] *= sc;
                O[nt][2 * ri + 1] *= sc;
            }
        }

        // ---- O += P V via per-warp staging ----
#pragma unroll
        for (int kt = 0; kt < 8; kt++) {
            *(float2*)&sPw[g * 12 + 2 * t] = make_float2(c[kt][0], c[kt][1]);
            *(float2*)&sPw[(g + 8) * 12 + 2 * t] = make_float2(c[kt][2], c[kt][3]);
            __syncwarp();
            float pa0 = sPw[g * 12 + t];
            float pa1 = sPw[(g + 8) * 12 + t];
            float pa2 = sPw[g * 12 + t + 4];
            float pa3 = sPw[(g + 8) * 12 + t + 4];
            __syncwarp();
            uint32_t ahi[4], alo[4];
            ahi[0] = f2tf(pa0); ahi[1] = f2tf(pa1);
            ahi[2] = f2tf(pa2); ahi[3] = f2tf(pa3);
            alo[0] = f2tf(pa0 - __uint_as_float(ahi[0]));
            alo[1] = f2tf(pa1 - __uint_as_float(ahi[1]));
            alo[2] = f2tf(pa2 - __uint_as_float(ahi[2]));
            alo[3] = f2tf(pa3 - __uint_as_float(ahi[3]));
            const int k0 = kt * 8;
#pragma unroll
            for (int nt = 0; nt < 16; nt++) {
                uint32_t b0 = sVu[(k0 + t) * VSTR + nt * 8 + g];
                uint32_t b1 = sVu[(k0 + t + 4) * VSTR + nt * 8 + g];
                mma_tf32(O[nt], ahi, b0, b1);
                mma_tf32(O[nt], alo, b0, b1);
            }
        }
    }

    // ---- epilogue: normalize and store ----
    float inv0 = 1.0f / l_i[0];
    float inv1 = 1.0f / l_i[1];
    size_t row0 = (size_t)b * TT + q0 + mBase + g;
    size_t row1 = row0 + 8;
#pragma unroll
    for (int nt = 0; nt < 16; nt++) {
        int col = nt * 8 + 2 * t;
        *(float2*)&out[row0 * DD + col] = make_float2(O[nt][0] * inv0, O[nt][1] * inv0);
        *(float2*)&out[row1 * DD + col] = make_float2(O[nt][2] * inv1, O[nt][3] * inv1);
    }
}

// ---------------------------------------------------------------------------
extern "C" void kernel_launch(void* const* d_in, const int* in_sizes, int n_in,
                              void* d_out, int out_size) {
    const float* x = (const float*)d_in[0];   // [8, 4096, 1024] fp32
    const float* W = (const float*)d_in[1];   // [128, 1024] fp32
    float* out = (float*)d_out;               // [8, 4096, 128] fp32

    cudaFuncSetAttribute(attn_kernel, cudaFuncAttributeMaxDynamicSharedMemorySize,
                         ATT_SMEM);

    proj_rope_kernel<<<(BB * TT) / 64, 128>>>(x, W);
    attn_kernel<<<dim3(64, BB), 128, ATT_SMEM>>>(out);
}